// round 15
// baseline (speedup 1.0000x reference)
#include <cuda_runtime.h>
#include <cuda_fp16.h>
#include <cstdint>
#include <math.h>

#define BB 4
#define SSZ 2048
#define DDIM 128
#define EPSV 1e-5f
#define KSCL 256.0f
#define IKSCL (1.0f / 256.0f)

// ---------------- scratch (static device globals; no allocations) ----------
__device__ float g_qnorm[BB * SSZ];
__device__ float g_knorm[BB * SSZ];
__device__ float g_partial[BB * SSZ * 16];
__device__ __half g_qhi[BB * SSZ * DDIM];            // fp16(q)
__device__ __half g_khi[BB * SSZ * DDIM];            // fp16(256*k) hi
__device__ __half g_klo[BB * SSZ * DDIM];            // fp16 residual of 256*k
__device__ __half g_vthi[BB * DDIM * SSZ];           // V^T hi: [b][d][t]
__device__ __half g_vtlo[BB * DDIM * SSZ];           // V^T lo
__device__ __half g_ph[(size_t)BB * SSZ * SSZ];      // unnormalized p (fp16)

// ---------------- helpers ---------------------------------------------------
__device__ __forceinline__ uint32_t smem_u32(const void* p) {
    uint32_t a;
    asm("{ .reg .u64 t; cvta.to.shared.u64 t, %1; cvt.u32.u64 %0, t; }" : "=r"(a) : "l"(p));
    return a;
}
__device__ __forceinline__ void cpa16(uint32_t s, const void* g) {
    asm volatile("cp.async.cg.shared.global [%0], [%1], 16;" :: "r"(s), "l"(g));
}
#define CP_COMMIT() asm volatile("cp.async.commit_group;")
#define CP_WAIT(n)  asm volatile("cp.async.wait_group %0;" :: "n"(n))

__device__ __forceinline__ void ldm_x4(uint32_t r[4], uint32_t addr) {
    asm volatile("ldmatrix.sync.aligned.m8n8.x4.shared.b16 {%0,%1,%2,%3}, [%4];"
        : "=r"(r[0]), "=r"(r[1]), "=r"(r[2]), "=r"(r[3]) : "r"(addr));
}
// D += A*B  (m16n8k16, fp16 in, f32 accum)
__device__ __forceinline__ void mma16816(float c[4], const uint32_t a[4],
                                         uint32_t b0, uint32_t b1) {
    asm volatile("mma.sync.aligned.m16n8k16.row.col.f32.f16.f16.f32 "
        "{%0,%1,%2,%3}, {%4,%5,%6,%7}, {%8,%9}, {%0,%1,%2,%3};"
        : "+f"(c[0]), "+f"(c[1]), "+f"(c[2]), "+f"(c[3])
        : "r"(a[0]), "r"(a[1]), "r"(a[2]), "r"(a[3]), "r"(b0), "r"(b1));
}
__device__ __forceinline__ __half2 h2(float a, float b) {
    return __floats2half2_rn(a, b);
}

// fast ln(x), x > 0; cephes-style range-reduced poly, ~1e-7 rel. FMA-pipe only.
__device__ __forceinline__ float fast_ln(float x) {
    int xi = __float_as_int(x);
    int e = ((xi >> 23) & 0xFF) - 126;                          // m in [0.5,1)
    float m = __int_as_float((xi & 0x007FFFFF) | 0x3F000000);
    if (m < 0.70710678f) { m += m; e -= 1; }                    // m in [.7071,1.4142)
    float t = m - 1.0f;
    float z = t * t;
    float p = 7.0376836292e-2f;
    p = fmaf(p, t, -1.1514610310e-1f);
    p = fmaf(p, t,  1.1676998740e-1f);
    p = fmaf(p, t, -1.2420140846e-1f);
    p = fmaf(p, t,  1.4249322787e-1f);
    p = fmaf(p, t, -1.6668057665e-1f);
    p = fmaf(p, t,  2.0000714765e-1f);
    p = fmaf(p, t, -2.4999993993e-1f);
    p = fmaf(p, t,  3.3333331174e-1f);
    float y = t * z * p;
    y = fmaf(-0.5f, z, y);
    return fmaf((float)e, 0.693147180559945f, t + y);
}

// fast 2^y for y in [-64, 0]; rint split + degree-6 poly, ~1e-7 rel.
__device__ __forceinline__ float fast_exp2(float y) {
    int i = __float2int_rn(y);
    float f = y - (float)i;                                     // f in [-0.5, 0.5]
    float p = 1.535336188319500e-4f;
    p = fmaf(p, f, 1.339887440266574e-3f);
    p = fmaf(p, f, 9.618437357674640e-3f);
    p = fmaf(p, f, 5.550332471162809e-2f);
    p = fmaf(p, f, 2.402264791363012e-1f);
    p = fmaf(p, f, 6.931472028550421e-1f);
    p = fmaf(p, f, 1.0f);
    float s = __int_as_float((i + 127) << 23);
    return p * s;
}

// ---------------- Kernel 1: row norms + q fp16 + k(scaled) fp16 hi/lo -------
__global__ __launch_bounds__(256) void hyp_norms(const float* __restrict__ q,
                                                 const float* __restrict__ k) {
    int warp = (blockIdx.x * blockDim.x + threadIdx.x) >> 5;
    int lane = threadIdx.x & 31;
    const int R = BB * SSZ;
    if (warp >= 2 * R) return;
    const bool isq = warp < R;
    const int row = isq ? warp : warp - R;
    const float* src = (isq ? q : k) + (size_t)row * DDIM;
    float4 v = ((const float4*)src)[lane];
    float s = v.x * v.x + v.y * v.y + v.z * v.z + v.w * v.w;
#pragma unroll
    for (int o = 16; o; o >>= 1) s += __shfl_xor_sync(0xffffffffu, s, o);
    if (lane == 0) { if (isq) g_qnorm[row] = s; else g_knorm[row] = s; }

    if (isq) {
        __half* hp = g_qhi + (size_t)row * DDIM + lane * 4;
        *(__half2*)(hp)     = h2(v.x, v.y);
        *(__half2*)(hp + 2) = h2(v.z, v.w);
    } else {
        float4 vs = make_float4(v.x * KSCL, v.y * KSCL, v.z * KSCL, v.w * KSCL);
        __half2 h0 = h2(vs.x, vs.y), h1 = h2(vs.z, vs.w);
        __half2 l0 = h2(vs.x - __half2float(h0.x), vs.y - __half2float(h0.y));
        __half2 l1 = h2(vs.z - __half2float(h1.x), vs.w - __half2float(h1.y));
        __half* hp = g_khi + (size_t)row * DDIM + lane * 4;
        __half* lp = g_klo + (size_t)row * DDIM + lane * 4;
        *(__half2*)(hp)     = h0;
        *(__half2*)(hp + 2) = h1;
        *(__half2*)(lp)     = l0;
        *(__half2*)(lp + 2) = l1;
    }
}

// ---------------- Kernel 2: V^T + fp16 hi/lo split ---------------------------
__global__ void hyp_vt(const float* __restrict__ v) {
    __shared__ float tile[32][33];
    const int b = blockIdx.z, t0 = blockIdx.x * 32, d0 = blockIdx.y * 32;
    const int tx = threadIdx.x, ty = threadIdx.y;
#pragma unroll
    for (int i = 0; i < 4; i++)
        tile[ty + 8 * i][tx] = v[((size_t)(b * SSZ) + t0 + ty + 8 * i) * DDIM + d0 + tx];
    __syncthreads();
#pragma unroll
    for (int i = 0; i < 4; i++) {
        float x = tile[tx][ty + 8 * i];
        __half hi = __float2half_rn(x);
        __half lo = __float2half_rn(x - __half2float(hi));
        size_t idx = ((size_t)(b * DDIM) + d0 + ty + 8 * i) * SSZ + t0 + tx;
        g_vthi[idx] = hi; g_vtlo[idx] = lo;
    }
}

// ---------------- Kernel 3: QK^T (fp16, 2 products) + hyperbolic numerator --
// 128x128 tile/CTA, 8 warps 2x4, warp tile 64x32. Writes p as single fp16.
// Epilogue uses polynomial ln/exp2 (FMA pipe) -- MUFU only for rsqrt.
#define QPAD 136
#define QK_TB (128 * QPAD * 2)
#define QK_SMEM (4096 + 3 * QK_TB)
__global__ void __launch_bounds__(256, 1)
hyp_qk(const float* __restrict__ cp, const float* __restrict__ betap) {
    extern __shared__ __align__(16) char smem[];
    float* qn_s = (float*)smem;
    float* kn_s = (float*)(smem + 512);
    float* iq_s = (float*)(smem + 1024);
    float* ik_s = (float*)(smem + 1536);
    float* rp_s = (float*)(smem + 2048);
    const uint32_t sb = smem_u32(smem);
    const uint32_t t_qh = sb + 4096, t_kh = t_qh + QK_TB, t_kl = t_kh + QK_TB;

    const int tid = threadIdx.x, wid = tid >> 5, lane = tid & 31;
    const int bxx = blockIdx.x, b = blockIdx.z;
    const int row0 = blockIdx.y * 128, col0 = bxx * 128;
    const float c = *cp;

    if (tid < 128) {
        float qn = g_qnorm[b * SSZ + row0 + tid];
        float kn = g_knorm[b * SSZ + col0 + tid];
        qn_s[tid] = qn; kn_s[tid] = kn;
        iq_s[tid] = 1.f / fmaxf(1.f - c * qn, 1e-12f);
        ik_s[tid] = 1.f / fmaxf(1.f - c * kn, 1e-12f);
    }

    {
        const __half* gq_h = g_qhi + (size_t)(b * SSZ + row0) * DDIM;
        const __half* gk_h = g_khi + (size_t)(b * SSZ + col0) * DDIM;
        const __half* gk_l = g_klo + (size_t)(b * SSZ + col0) * DDIM;
#pragma unroll
        for (int it = 0; it < 8; it++) {
            int i = tid + 256 * it;
            int r = i >> 4, g = i & 15;
            uint32_t so = (uint32_t)(r * (QPAD * 2) + g * 16);
            size_t go = (size_t)r * DDIM + g * 8;
            cpa16(t_qh + so, gq_h + go);
            cpa16(t_kh + so, gk_h + go);
            cpa16(t_kl + so, gk_l + go);
        }
    }
    CP_COMMIT();
    CP_WAIT(0);
    __syncthreads();

    const int wr = wid >> 2, wc = wid & 3;
    const int m0 = wr * 64, n0 = wc * 32;
    const int alr = lane & 15, alc = (lane >> 4) * 8;

    float acc[4][4][4];
#pragma unroll
    for (int i = 0; i < 4; i++)
#pragma unroll
        for (int j = 0; j < 4; j++)
#pragma unroll
            for (int r = 0; r < 4; r++) acc[i][j][r] = 0.f;

#pragma unroll
    for (int ks = 0; ks < 8; ks++) {
        uint32_t ah[4][4], bh[2][4], bl[2][4];
        const int kel = ks * 16 + alc;
#pragma unroll
        for (int fm = 0; fm < 4; fm++) {
            uint32_t off = (uint32_t)(((m0 + fm * 16 + alr) * QPAD + kel) * 2);
            ldm_x4(ah[fm], t_qh + off);
        }
#pragma unroll
        for (int h = 0; h < 2; h++) {
            uint32_t off = (uint32_t)(((n0 + h * 16 + alr) * QPAD + kel) * 2);
            ldm_x4(bh[h], t_kh + off);
            ldm_x4(bl[h], t_kl + off);
        }
#pragma unroll
        for (int fm = 0; fm < 4; fm++)
#pragma unroll
            for (int fn = 0; fn < 4; fn++) {
                int h = fn >> 1, s = fn & 1;
                mma16816(acc[fm][fn], ah[fm], bh[h][s], bh[h][s + 2]);
                mma16816(acc[fm][fn], ah[fm], bl[h][s], bl[h][s + 2]);
            }
    }

    // epilogue: dot = acc/256; p = exp(-e2 * ln u), u = (1+x)+sqrt(x(x+2))
    const float sqrtc = sqrtf(c);
    const float beta = *betap;
    const float bp = fmaxf(beta, 0.f) + log1pf(expf(-fabsf(beta)));  // softplus
    const float e2l = (bp / sqrtc) * 1.4426950408889634f;  // * log2(e)
    const float tcc = 2.f * c;

    __half* ph = g_ph + ((size_t)(b * SSZ + row0)) * SSZ + col0;
#pragma unroll
    for (int fm = 0; fm < 4; fm++) {
        const int r1 = m0 + fm * 16 + (lane >> 2), r2 = r1 + 8;
        const float qn1 = qn_s[r1], qn2 = qn_s[r2];
        const float iq1 = iq_s[r1], iq2 = iq_s[r2];
        float s1 = 0.f, s2 = 0.f;
#pragma unroll
        for (int fn = 0; fn < 4; fn++) {
            const int cc = n0 + fn * 8 + (lane & 3) * 2;
            const float kn0 = kn_s[cc], kn1 = kn_s[cc + 1];
            const float ik0 = ik_s[cc], ik1 = ik_s[cc + 1];
            float pv[4];
#pragma unroll
            for (int rr = 0; rr < 2; rr++) {
                float qn = rr ? qn2 : qn1, iq = rr ? iq2 : iq1;
#pragma unroll
                for (int jj = 0; jj < 2; jj++) {
                    float dot = acc[fm][fn][rr * 2 + jj] * IKSCL;
                    float kn = jj ? kn1 : kn0, ik = jj ? ik1 : ik0;
                    float x = tcc * (qn + kn - 2.f * dot) * iq * ik;
                    x = fmaxf(x, EPSV);
                    float t = x * (x + 2.f);
                    float u = (1.f + x) + t * rsqrtf(t);
                    float p = fast_exp2(-e2l * fast_ln(u));
                    pv[rr * 2 + jj] = p;
                    if (rr) s2 += p; else s1 += p;
                }
            }
            *(__half2*)(ph + (size_t)r1 * SSZ + cc) = h2(pv[0], pv[1]);
            *(__half2*)(ph + (size_t)r2 * SSZ + cc) = h2(pv[2], pv[3]);
        }
        s1 += __shfl_xor_sync(0xffffffffu, s1, 1);
        s1 += __shfl_xor_sync(0xffffffffu, s1, 2);
        s2 += __shfl_xor_sync(0xffffffffu, s2, 1);
        s2 += __shfl_xor_sync(0xffffffffu, s2, 2);
        if ((lane & 3) == 0) {
            rp_s[r1 * 4 + wc] = s1;
            rp_s[r2 * 4 + wc] = s2;
        }
    }
    __syncthreads();
    if (tid < 128) {
        float s = rp_s[tid * 4] + rp_s[tid * 4 + 1] + rp_s[tid * 4 + 2] + rp_s[tid * 4 + 3];
        g_partial[((size_t)(b * SSZ + row0 + tid)) * 16 + bxx] = s;
    }
}

// ---------------- Kernel 4: O = expmap0((P V)/rowsum) + W = P/rowsum --------
// 32(M) x 128(N=D) per CTA => 256 CTAs. K=2048 in 64-chunks, cp.async 2-stage.
#define APAD 72
#define AV_WT (32 * APAD)
#define AV_VT (128 * APAD)
#define AV_BUF (AV_WT + 2 * AV_VT)
#define AV_SMEM (2048 + 2 * AV_BUF * 2)
__global__ void __launch_bounds__(256, 2)
hyp_av(const float* __restrict__ cp, float* __restrict__ W,
       float* __restrict__ out) {
    extern __shared__ __align__(16) char smem[];
    float* inv_s = (float*)smem;
    float* rp_s = (float*)(smem + 512);
    const uint32_t sb = smem_u32(smem);

    const int tid = threadIdx.x, wid = tid >> 5, lane = tid & 31;
    const int b = blockIdx.z;
    const int row0 = blockIdx.x * 32;

    if (tid < 32) {
        float s = 0.f;
#pragma unroll
        for (int i = 0; i < 16; i++)
            s += g_partial[((size_t)(b * SSZ + row0 + tid)) * 16 + i];
        inv_s[tid] = 1.f / s;
    }

    const __half* pb = g_ph + ((size_t)(b * SSZ + row0)) * SSZ;
    const __half* vth = g_vthi + (size_t)b * DDIM * SSZ;
    const __half* vtl = g_vtlo + (size_t)b * DDIM * SSZ;
    float* wrow = W + ((size_t)(b * SSZ + row0)) * SSZ;

    const uint32_t buf0 = sb + 2048;
    const uint32_t o_vh = AV_WT * 2, o_vl = o_vh + AV_VT * 2;

    auto load_chunk = [&](int stage, int t0) {
        uint32_t base = buf0 + stage * (AV_BUF * 2);
        {
            int r = tid >> 3, g = tid & 7;
            uint32_t so = (uint32_t)(r * (APAD * 2) + g * 16);
            cpa16(base + so, pb + (size_t)r * SSZ + t0 + g * 8);
        }
#pragma unroll
        for (int it = 0; it < 4; it++) {
            int i = tid + 256 * it;
            int d = i >> 3, g = i & 7;
            uint32_t so = (uint32_t)(d * (APAD * 2) + g * 16);
            size_t go = (size_t)d * SSZ + t0 + g * 8;
            cpa16(base + o_vh + so, vth + go);
            cpa16(base + o_vl + so, vtl + go);
        }
    };

    const int wr = wid >> 2, wc = wid & 3;
    const int m0 = wr * 16, n0 = wc * 32;
    const int alr = lane & 15, alc = (lane >> 4) * 8;

    const int er = tid >> 3, ecg = (tid & 7) * 8;

    float acc[4][4];
#pragma unroll
    for (int j = 0; j < 4; j++)
#pragma unroll
        for (int r = 0; r < 4; r++) acc[j][r] = 0.f;

    load_chunk(0, 0);
    CP_COMMIT();

    for (int kc = 0; kc < 32; kc++) {
        if (kc < 31) {
            load_chunk((kc + 1) & 1, (kc + 1) * 64);
            CP_COMMIT();
            CP_WAIT(1);
        } else {
            CP_WAIT(0);
        }
        __syncthreads();

        uint32_t base = buf0 + (kc & 1) * (AV_BUF * 2);

        // --- emit normalized fp32 W tile from resident p chunk ---
        {
            const float inv = inv_s[er];
            const char* sp = smem + 2048 + (kc & 1) * (AV_BUF * 2);
            uint4 hu = *(const uint4*)(sp + er * (APAD * 2) + ecg * 2);
            const __half2* hp = (const __half2*)&hu;
            float4 w0, w1;
            w0.x = __half2float(hp[0].x) * inv;
            w0.y = __half2float(hp[0].y) * inv;
            w0.z = __half2float(hp[1].x) * inv;
            w0.w = __half2float(hp[1].y) * inv;
            w1.x = __half2float(hp[2].x) * inv;
            w1.y = __half2float(hp[2].y) * inv;
            w1.z = __half2float(hp[3].x) * inv;
            w1.w = __half2float(hp[3].y) * inv;
            float* wdst = wrow + (size_t)er * SSZ + kc * 64 + ecg;
            *(float4*)(wdst)     = w0;
            *(float4*)(wdst + 4) = w1;
        }

#pragma unroll
        for (int ks = 0; ks < 4; ks++) {
            uint32_t ah[4], bh[2][4], bl[2][4];
            const int kel = ks * 16 + alc;
            {
                uint32_t off = (uint32_t)(((m0 + alr) * APAD + kel) * 2);
                ldm_x4(ah, base + off);
            }
#pragma unroll
            for (int h = 0; h < 2; h++) {
                uint32_t off = (uint32_t)(((n0 + h * 16 + alr) * APAD + kel) * 2);
                ldm_x4(bh[h], base + o_vh + off);
                ldm_x4(bl[h], base + o_vl + off);
            }
#pragma unroll
            for (int fn = 0; fn < 4; fn++) {
                int h = fn >> 1, s = fn & 1;
                mma16816(acc[fn], ah, bh[h][s], bh[h][s + 2]);
                mma16816(acc[fn], ah, bl[h][s], bl[h][s + 2]);
            }
        }
        __syncthreads();
    }

    // epilogue: normalize by rowsum, then exp-map at origin
    const int r1 = m0 + (lane >> 2), r2 = r1 + 8;
    const float i1 = inv_s[r1], i2 = inv_s[r2];
    float s1 = 0.f, s2 = 0.f;
#pragma unroll
    for (int fn = 0; fn < 4; fn++) {
        acc[fn][0] *= i1; acc[fn][1] *= i1;
        acc[fn][2] *= i2; acc[fn][3] *= i2;
        s1 += acc[fn][0] * acc[fn][0] + acc[fn][1] * acc[fn][1];
        s2 += acc[fn][2] * acc[fn][2] + acc[fn][3] * acc[fn][3];
    }
    s1 += __shfl_xor_sync(0xffffffffu, s1, 1);
    s1 += __shfl_xor_sync(0xffffffffu, s1, 2);
    s2 += __shfl_xor_sync(0xffffffffu, s2, 1);
    s2 += __shfl_xor_sync(0xffffffffu, s2, 2);
    if ((lane & 3) == 0) {
        rp_s[r1 * 4 + wc] = s1;
        rp_s[r2 * 4 + wc] = s2;
    }
    __syncthreads();
    const float c = *cp, sqrtc = sqrtf(c);
    float* sc_s = (float*)(smem + 256);
    if (tid < 32) {
        float ns = rp_s[tid * 4] + rp_s[tid * 4 + 1] + rp_s[tid * 4 + 2] + rp_s[tid * 4 + 3];
        float vn = fmaxf(sqrtf(ns), EPSV);
        sc_s[tid] = tanhf(sqrtc * vn) / (sqrtc * vn);
    }
    __syncthreads();

    float* ob = out + ((size_t)(b * SSZ + row0)) * DDIM;
    const float sc1 = sc_s[r1], sc2 = sc_s[r2];
#pragma unroll
    for (int fn = 0; fn < 4; fn++) {
        const int cc = n0 + fn * 8 + (lane & 3) * 2;
        *(float2*)(ob + (size_t)r1 * DDIM + cc) =
            make_float2(acc[fn][0] * sc1, acc[fn][1] * sc1);
        *(float2*)(ob + (size_t)r2 * DDIM + cc) =
            make_float2(acc[fn][2] * sc2, acc[fn][3] * sc2);
    }
}

// ---------------------------------------------------------------------------
extern "C" void kernel_launch(void* const* d_in, const int* in_sizes, int n_in,
                              void* d_out, int out_size) {
    const float* q    = (const float*)d_in[0];
    const float* k    = (const float*)d_in[1];
    const float* v    = (const float*)d_in[2];
    const float* c    = (const float*)d_in[3];
    const float* beta = (const float*)d_in[4];

    float* out = (float*)d_out;                   // output_hyperbolic (B,S,D)
    float* W   = out + (size_t)BB * SSZ * DDIM;   // attention_weights (B,S,S)

    cudaFuncSetAttribute(hyp_qk, cudaFuncAttributeMaxDynamicSharedMemorySize, QK_SMEM);
    cudaFuncSetAttribute(hyp_av, cudaFuncAttributeMaxDynamicSharedMemorySize, AV_SMEM);

    hyp_norms<<<2 * BB * SSZ / 8, 256>>>(q, k);
    hyp_vt<<<dim3(SSZ / 32, DDIM / 32, BB), dim3(32, 8)>>>(v);
    hyp_qk<<<dim3(SSZ / 128, SSZ / 128, BB), 256, QK_SMEM>>>(c, beta);
    hyp_av<<<dim3(SSZ / 32, 1, BB), 256, AV_SMEM>>>(c, W, out);
}

// round 16
// speedup vs baseline: 1.4329x; 1.4329x over previous
#include <cuda_runtime.h>
#include <cuda_fp16.h>
#include <cstdint>
#include <math.h>

#define BB 4
#define SSZ 2048
#define DDIM 128
#define EPSV 1e-5f

// ---------------- scratch (static device globals; no allocations) ----------
__device__ float g_qnorm[BB * SSZ];
__device__ float g_knorm[BB * SSZ];
__device__ float g_partial[BB * SSZ * 16];
__device__ __half g_qh[BB * SSZ * DDIM];             // fp16(q)
__device__ __half g_kh[BB * SSZ * DDIM];             // fp16(k)
__device__ __half g_vt[BB * DDIM * SSZ];             // V^T fp16: [b][d][t]
__device__ __half g_ph[(size_t)BB * SSZ * SSZ];      // unnormalized p (fp16)

// ---------------- helpers ---------------------------------------------------
__device__ __forceinline__ uint32_t smem_u32(const void* p) {
    uint32_t a;
    asm("{ .reg .u64 t; cvta.to.shared.u64 t, %1; cvt.u32.u64 %0, t; }" : "=r"(a) : "l"(p));
    return a;
}
__device__ __forceinline__ void cpa16(uint32_t s, const void* g) {
    asm volatile("cp.async.cg.shared.global [%0], [%1], 16;" :: "r"(s), "l"(g));
}
#define CP_COMMIT() asm volatile("cp.async.commit_group;")
#define CP_WAIT(n)  asm volatile("cp.async.wait_group %0;" :: "n"(n))

__device__ __forceinline__ void ldm_x4(uint32_t r[4], uint32_t addr) {
    asm volatile("ldmatrix.sync.aligned.m8n8.x4.shared.b16 {%0,%1,%2,%3}, [%4];"
        : "=r"(r[0]), "=r"(r[1]), "=r"(r[2]), "=r"(r[3]) : "r"(addr));
}
// D += A*B  (m16n8k16, fp16 in, f32 accum)
__device__ __forceinline__ void mma16816(float c[4], const uint32_t a[4],
                                         uint32_t b0, uint32_t b1) {
    asm volatile("mma.sync.aligned.m16n8k16.row.col.f32.f16.f16.f32 "
        "{%0,%1,%2,%3}, {%4,%5,%6,%7}, {%8,%9}, {%0,%1,%2,%3};"
        : "+f"(c[0]), "+f"(c[1]), "+f"(c[2]), "+f"(c[3])
        : "r"(a[0]), "r"(a[1]), "r"(a[2]), "r"(a[3]), "r"(b0), "r"(b1));
}
__device__ __forceinline__ __half2 h2(float a, float b) {
    return __floats2half2_rn(a, b);
}

// ---------------- Kernel 1: row norms + q,k -> fp16 --------------------------
__global__ __launch_bounds__(256) void hyp_norms(const float* __restrict__ q,
                                                 const float* __restrict__ k) {
    int warp = (blockIdx.x * blockDim.x + threadIdx.x) >> 5;
    int lane = threadIdx.x & 31;
    const int R = BB * SSZ;
    if (warp >= 2 * R) return;
    const bool isq = warp < R;
    const int row = isq ? warp : warp - R;
    const float* src = (isq ? q : k) + (size_t)row * DDIM;
    float4 v = ((const float4*)src)[lane];
    float s = v.x * v.x + v.y * v.y + v.z * v.z + v.w * v.w;
#pragma unroll
    for (int o = 16; o; o >>= 1) s += __shfl_xor_sync(0xffffffffu, s, o);
    if (lane == 0) { if (isq) g_qnorm[row] = s; else g_knorm[row] = s; }

    __half* hp = (isq ? g_qh : g_kh) + (size_t)row * DDIM + lane * 4;
    *(__half2*)(hp)     = h2(v.x, v.y);
    *(__half2*)(hp + 2) = h2(v.z, v.w);
}

// ---------------- Kernel 2: V^T fp16 ----------------------------------------
__global__ void hyp_vt(const float* __restrict__ v) {
    __shared__ float tile[32][33];
    const int b = blockIdx.z, t0 = blockIdx.x * 32, d0 = blockIdx.y * 32;
    const int tx = threadIdx.x, ty = threadIdx.y;
#pragma unroll
    for (int i = 0; i < 4; i++)
        tile[ty + 8 * i][tx] = v[((size_t)(b * SSZ) + t0 + ty + 8 * i) * DDIM + d0 + tx];
    __syncthreads();
#pragma unroll
    for (int i = 0; i < 4; i++) {
        float x = tile[tx][ty + 8 * i];
        size_t idx = ((size_t)(b * DDIM) + d0 + ty + 8 * i) * SSZ + t0 + tx;
        g_vt[idx] = __float2half_rn(x);
    }
}

// ---------------- Kernel 3: QK^T (fp16, single product) + hyperbolic p ------
// 128x128 tile/CTA, 8 warps 2x4, warp tile 64x32. Writes p as single fp16.
#define QPAD 136
#define QK_TB (128 * QPAD * 2)
#define QK_SMEM (4096 + 2 * QK_TB)
__global__ void __launch_bounds__(256, 1)
hyp_qk(const float* __restrict__ cp, const float* __restrict__ betap) {
    extern __shared__ __align__(16) char smem[];
    float* qn_s = (float*)smem;
    float* kn_s = (float*)(smem + 512);
    float* iq_s = (float*)(smem + 1024);
    float* ik_s = (float*)(smem + 1536);
    float* rp_s = (float*)(smem + 2048);
    const uint32_t sb = smem_u32(smem);
    const uint32_t t_qh = sb + 4096, t_kh = t_qh + QK_TB;

    const int tid = threadIdx.x, wid = tid >> 5, lane = tid & 31;
    const int bxx = blockIdx.x, b = blockIdx.z;
    const int row0 = blockIdx.y * 128, col0 = bxx * 128;
    const float c = *cp;

    if (tid < 128) {
        float qn = g_qnorm[b * SSZ + row0 + tid];
        float kn = g_knorm[b * SSZ + col0 + tid];
        qn_s[tid] = qn; kn_s[tid] = kn;
        iq_s[tid] = 1.f / fmaxf(1.f - c * qn, 1e-12f);
        ik_s[tid] = 1.f / fmaxf(1.f - c * kn, 1e-12f);
    }

    {
        const __half* gq = g_qh + (size_t)(b * SSZ + row0) * DDIM;
        const __half* gk = g_kh + (size_t)(b * SSZ + col0) * DDIM;
#pragma unroll
        for (int it = 0; it < 8; it++) {
            int i = tid + 256 * it;
            int r = i >> 4, g = i & 15;
            uint32_t so = (uint32_t)(r * (QPAD * 2) + g * 16);
            size_t go = (size_t)r * DDIM + g * 8;
            cpa16(t_qh + so, gq + go);
            cpa16(t_kh + so, gk + go);
        }
    }
    CP_COMMIT();
    CP_WAIT(0);
    __syncthreads();

    const int wr = wid >> 2, wc = wid & 3;
    const int m0 = wr * 64, n0 = wc * 32;
    const int alr = lane & 15, alc = (lane >> 4) * 8;

    float acc[4][4][4];
#pragma unroll
    for (int i = 0; i < 4; i++)
#pragma unroll
        for (int j = 0; j < 4; j++)
#pragma unroll
            for (int r = 0; r < 4; r++) acc[i][j][r] = 0.f;

#pragma unroll
    for (int ks = 0; ks < 8; ks++) {
        uint32_t ah[4][4], bh[2][4];
        const int kel = ks * 16 + alc;
#pragma unroll
        for (int fm = 0; fm < 4; fm++) {
            uint32_t off = (uint32_t)(((m0 + fm * 16 + alr) * QPAD + kel) * 2);
            ldm_x4(ah[fm], t_qh + off);
        }
#pragma unroll
        for (int h = 0; h < 2; h++) {
            uint32_t off = (uint32_t)(((n0 + h * 16 + alr) * QPAD + kel) * 2);
            ldm_x4(bh[h], t_kh + off);
        }
#pragma unroll
        for (int fm = 0; fm < 4; fm++)
#pragma unroll
            for (int fn = 0; fn < 4; fn++) {
                int h = fn >> 1, s = fn & 1;
                mma16816(acc[fm][fn], ah[fm], bh[h][s], bh[h][s + 2]);
            }
    }

    // epilogue: p = u^(-bp/sqrt(c)), u = (1+x)+sqrt(x(x+2)); bias cancels
    const float sqrtc = sqrtf(c);
    const float beta = *betap;
    const float bp = fmaxf(beta, 0.f) + log1pf(expf(-fabsf(beta)));  // softplus
    const float e2 = bp / sqrtc;
    const float tcc = 2.f * c;

    __half* ph = g_ph + ((size_t)(b * SSZ + row0)) * SSZ + col0;
#pragma unroll
    for (int fm = 0; fm < 4; fm++) {
        const int r1 = m0 + fm * 16 + (lane >> 2), r2 = r1 + 8;
        const float qn1 = qn_s[r1], qn2 = qn_s[r2];
        const float iq1 = iq_s[r1], iq2 = iq_s[r2];
        float s1 = 0.f, s2 = 0.f;
#pragma unroll
        for (int fn = 0; fn < 4; fn++) {
            const int cc = n0 + fn * 8 + (lane & 3) * 2;
            const float kn0 = kn_s[cc], kn1 = kn_s[cc + 1];
            const float ik0 = ik_s[cc], ik1 = ik_s[cc + 1];
            float pv[4];
#pragma unroll
            for (int rr = 0; rr < 2; rr++) {
                float qn = rr ? qn2 : qn1, iq = rr ? iq2 : iq1;
#pragma unroll
                for (int jj = 0; jj < 2; jj++) {
                    float dot = acc[fm][fn][rr * 2 + jj];
                    float kn = jj ? kn1 : kn0, ik = jj ? ik1 : ik0;
                    float x = tcc * (qn + kn - 2.f * dot) * iq * ik;
                    x = fmaxf(x, EPSV);
                    float t = x * (x + 2.f);
                    float u = (1.f + x) + t * rsqrtf(t);
                    float p = exp2f(-e2 * __log2f(u));
                    pv[rr * 2 + jj] = p;
                    if (rr) s2 += p; else s1 += p;
                }
            }
            *(__half2*)(ph + (size_t)r1 * SSZ + cc) = h2(pv[0], pv[1]);
            *(__half2*)(ph + (size_t)r2 * SSZ + cc) = h2(pv[2], pv[3]);
        }
        s1 += __shfl_xor_sync(0xffffffffu, s1, 1);
        s1 += __shfl_xor_sync(0xffffffffu, s1, 2);
        s2 += __shfl_xor_sync(0xffffffffu, s2, 1);
        s2 += __shfl_xor_sync(0xffffffffu, s2, 2);
        if ((lane & 3) == 0) {
            rp_s[r1 * 4 + wc] = s1;
            rp_s[r2 * 4 + wc] = s2;
        }
    }
    __syncthreads();
    if (tid < 128) {
        float s = rp_s[tid * 4] + rp_s[tid * 4 + 1] + rp_s[tid * 4 + 2] + rp_s[tid * 4 + 3];
        g_partial[((size_t)(b * SSZ + row0 + tid)) * 16 + bxx] = s;
    }
}

// ---------------- Kernel 4: O = expmap0((P V)/rowsum) + W = P/rowsum --------
// 32(M) x 128(N=D) per CTA => 256 CTAs. K=2048 in 64-chunks, cp.async 2-stage.
// Single-fp16 V (no residual product).
#define APAD 72
#define AV_WT (32 * APAD)
#define AV_VT (128 * APAD)
#define AV_BUF (AV_WT + AV_VT)
#define AV_SMEM (2048 + 2 * AV_BUF * 2)
__global__ void __launch_bounds__(256, 2)
hyp_av(const float* __restrict__ cp, float* __restrict__ W,
       float* __restrict__ out) {
    extern __shared__ __align__(16) char smem[];
    float* inv_s = (float*)smem;
    float* rp_s = (float*)(smem + 512);
    const uint32_t sb = smem_u32(smem);

    const int tid = threadIdx.x, wid = tid >> 5, lane = tid & 31;
    const int b = blockIdx.z;
    const int row0 = blockIdx.x * 32;

    if (tid < 32) {
        float s = 0.f;
#pragma unroll
        for (int i = 0; i < 16; i++)
            s += g_partial[((size_t)(b * SSZ + row0 + tid)) * 16 + i];
        inv_s[tid] = 1.f / s;
    }

    const __half* pb = g_ph + ((size_t)(b * SSZ + row0)) * SSZ;
    const __half* vt = g_vt + (size_t)b * DDIM * SSZ;
    float* wrow = W + ((size_t)(b * SSZ + row0)) * SSZ;

    const uint32_t buf0 = sb + 2048;
    const uint32_t o_vh = AV_WT * 2;

    auto load_chunk = [&](int stage, int t0) {
        uint32_t base = buf0 + stage * (AV_BUF * 2);
        {
            int r = tid >> 3, g = tid & 7;
            uint32_t so = (uint32_t)(r * (APAD * 2) + g * 16);
            cpa16(base + so, pb + (size_t)r * SSZ + t0 + g * 8);
        }
#pragma unroll
        for (int it = 0; it < 4; it++) {
            int i = tid + 256 * it;
            int d = i >> 3, g = i & 7;
            uint32_t so = (uint32_t)(d * (APAD * 2) + g * 16);
            cpa16(base + o_vh + so, vt + (size_t)d * SSZ + t0 + g * 8);
        }
    };

    const int wr = wid >> 2, wc = wid & 3;
    const int m0 = wr * 16, n0 = wc * 32;
    const int alr = lane & 15, alc = (lane >> 4) * 8;

    const int er = tid >> 3, ecg = (tid & 7) * 8;

    float acc[4][4];
#pragma unroll
    for (int j = 0; j < 4; j++)
#pragma unroll
        for (int r = 0; r < 4; r++) acc[j][r] = 0.f;

    load_chunk(0, 0);
    CP_COMMIT();

    for (int kc = 0; kc < 32; kc++) {
        if (kc < 31) {
            load_chunk((kc + 1) & 1, (kc + 1) * 64);
            CP_COMMIT();
            CP_WAIT(1);
        } else {
            CP_WAIT(0);
        }
        __syncthreads();

        uint32_t base = buf0 + (kc & 1) * (AV_BUF * 2);

        // --- emit normalized fp32 W tile from resident p chunk ---
        {
            const float inv = inv_s[er];
            const char* sp = smem + 2048 + (kc & 1) * (AV_BUF * 2);
            uint4 hu = *(const uint4*)(sp + er * (APAD * 2) + ecg * 2);
            const __half2* hp = (const __half2*)&hu;
            float4 w0, w1;
            w0.x = __half2float(hp[0].x) * inv;
            w0.y = __half2float(hp[0].y) * inv;
            w0.z = __half2float(hp[1].x) * inv;
            w0.w = __half2float(hp[1].y) * inv;
            w1.x = __half2float(hp[2].x) * inv;
            w1.y = __half2float(hp[2].y) * inv;
            w1.z = __half2float(hp[3].x) * inv;
            w1.w = __half2float(hp[3].y) * inv;
            float* wdst = wrow + (size_t)er * SSZ + kc * 64 + ecg;
            *(float4*)(wdst)     = w0;
            *(float4*)(wdst + 4) = w1;
        }

#pragma unroll
        for (int ks = 0; ks < 4; ks++) {
            uint32_t ah[4], bh[2][4];
            const int kel = ks * 16 + alc;
            {
                uint32_t off = (uint32_t)(((m0 + alr) * APAD + kel) * 2);
                ldm_x4(ah, base + off);
            }
#pragma unroll
            for (int h = 0; h < 2; h++) {
                uint32_t off = (uint32_t)(((n0 + h * 16 + alr) * APAD + kel) * 2);
                ldm_x4(bh[h], base + o_vh + off);
            }
#pragma unroll
            for (int fn = 0; fn < 4; fn++) {
                int h = fn >> 1, s = fn & 1;
                mma16816(acc[fn], ah, bh[h][s], bh[h][s + 2]);
            }
        }
        __syncthreads();
    }

    // epilogue: normalize by rowsum, then exp-map at origin
    const int r1 = m0 + (lane >> 2), r2 = r1 + 8;
    const float i1 = inv_s[r1], i2 = inv_s[r2];
    float s1 = 0.f, s2 = 0.f;
#pragma unroll
    for (int fn = 0; fn < 4; fn++) {
        acc[fn][0] *= i1; acc[fn][1] *= i1;
        acc[fn][2] *= i2; acc[fn][3] *= i2;
        s1 += acc[fn][0] * acc[fn][0] + acc[fn][1] * acc[fn][1];
        s2 += acc[fn][2] * acc[fn][2] + acc[fn][3] * acc[fn][3];
    }
    s1 += __shfl_xor_sync(0xffffffffu, s1, 1);
    s1 += __shfl_xor_sync(0xffffffffu, s1, 2);
    s2 += __shfl_xor_sync(0xffffffffu, s2, 1);
    s2 += __shfl_xor_sync(0xffffffffu, s2, 2);
    if ((lane & 3) == 0) {
        rp_s[r1 * 4 + wc] = s1;
        rp_s[r2 * 4 + wc] = s2;
    }
    __syncthreads();
    const float c = *cp, sqrtc = sqrtf(c);
    float* sc_s = (float*)(smem + 256);
    if (tid < 32) {
        float ns = rp_s[tid * 4] + rp_s[tid * 4 + 1] + rp_s[tid * 4 + 2] + rp_s[tid * 4 + 3];
        float vn = fmaxf(sqrtf(ns), EPSV);
        sc_s[tid] = tanhf(sqrtc * vn) / (sqrtc * vn);
    }
    __syncthreads();

    float* ob = out + ((size_t)(b * SSZ + row0)) * DDIM;
    const float sc1 = sc_s[r1], sc2 = sc_s[r2];
#pragma unroll
    for (int fn = 0; fn < 4; fn++) {
        const int cc = n0 + fn * 8 + (lane & 3) * 2;
        *(float2*)(ob + (size_t)r1 * DDIM + cc) =
            make_float2(acc[fn][0] * sc1, acc[fn][1] * sc1);
        *(float2*)(ob + (size_t)r2 * DDIM + cc) =
            make_float2(acc[fn][2] * sc2, acc[fn][3] * sc2);
    }
}

// ---------------------------------------------------------------------------
extern "C" void kernel_launch(void* const* d_in, const int* in_sizes, int n_in,
                              void* d_out, int out_size) {
    const float* q    = (const float*)d_in[0];
    const float* k    = (const float*)d_in[1];
    const float* v    = (const float*)d_in[2];
    const float* c    = (const float*)d_in[3];
    const float* beta = (const float*)d_in[4];

    float* out = (float*)d_out;                   // output_hyperbolic (B,S,D)
    float* W   = out + (size_t)BB * SSZ * DDIM;   // attention_weights (B,S,S)

    cudaFuncSetAttribute(hyp_qk, cudaFuncAttributeMaxDynamicSharedMemorySize, QK_SMEM);
    cudaFuncSetAttribute(hyp_av, cudaFuncAttributeMaxDynamicSharedMemorySize, AV_SMEM);

    hyp_norms<<<2 * BB * SSZ / 8, 256>>>(q, k);
    hyp_vt<<<dim3(SSZ / 32, DDIM / 32, BB), dim3(32, 8)>>>(v);
    hyp_qk<<<dim3(SSZ / 128, SSZ / 128, BB), 256, QK_SMEM>>>(c, beta);
    hyp_av<<<dim3(SSZ / 32, 1, BB), 256, AV_SMEM>>>(c, W, out);
}